// round 13
// baseline (speedup 1.0000x reference)
#include <cuda_runtime.h>
#include <math.h>

#define NEGF    (-1e30f)
#define MAXB    16
#define NCH     32
#define LOG2E_F 1.4426950408889634f
#define LN2_F   0.6931471805599453f

// Scratch (static device arrays; no allocations allowed)
__device__ float    g_num[MAXB];                 // numerator logZ per batch (natural log)
__device__ float    g_LP[MAXB * NCH * 8 * 8];    // [b][c][j][i] log chunk matrices
__device__ unsigned g_done = 0;

// ---------------- helpers ----------------
__device__ __forceinline__ float ex2f_(float x) {
    float r; asm("ex2.approx.ftz.f32 %0, %1;" : "=f"(r) : "f"(x)); return r;
}
__device__ __forceinline__ float lg2f_(float x) {
    float r; asm("lg2.approx.ftz.f32 %0, %1;" : "=f"(r) : "f"(x)); return r;
}
__device__ __forceinline__ float lae2(float a, float b) {
    float m = fmaxf(a, b);
    float d = fminf(a, b) - m;
    return m + lg2f_(1.0f + ex2f_(d));
}
__device__ __forceinline__ float4 lds128v(const float4* p) {
    float4 v; unsigned a = (unsigned)__cvta_generic_to_shared(p);
    asm volatile("ld.volatile.shared.v4.f32 {%0,%1,%2,%3},[%4];"
                 : "=f"(v.x), "=f"(v.y), "=f"(v.z), "=f"(v.w) : "r"(a));
    return v;
}
__device__ __forceinline__ float lds32v(const float* p) {
    float v; unsigned a = (unsigned)__cvta_generic_to_shared(p);
    asm volatile("ld.volatile.shared.f32 %0,[%1];" : "=f"(v) : "r"(a));
    return v;
}
__device__ __forceinline__ void sts128v(float4* p, float4 v) {
    unsigned a = (unsigned)__cvta_generic_to_shared(p);
    asm volatile("st.volatile.shared.v4.f32 [%0],{%1,%2,%3,%4};"
                 :: "r"(a), "f"(v.x), "f"(v.y), "f"(v.z), "f"(v.w));
}
__device__ __forceinline__ void sts32v(float* p, float v) {
    unsigned a = (unsigned)__cvta_generic_to_shared(p);
    asm volatile("st.volatile.shared.f32 [%0],%1;" :: "r"(a), "f"(v));
}
__device__ __forceinline__ void sts128v_pred(float4* p, float4 v, int doit) {
    unsigned a = (unsigned)__cvta_generic_to_shared(p);
    asm volatile("{ .reg .pred p0;\n\t"
                 "setp.ne.u32 p0, %0, 0;\n\t"
                 "@p0 st.volatile.shared.v4.f32 [%1],{%2,%3,%4,%5}; }"
                 :: "r"(doit), "r"(a), "f"(v.x), "f"(v.y), "f"(v.z), "f"(v.w));
}
__device__ __forceinline__ void sts32v_pred(float* p, float v, int doit) {
    unsigned a = (unsigned)__cvta_generic_to_shared(p);
    asm volatile("{ .reg .pred p0;\n\t"
                 "setp.ne.u32 p0, %0, 0;\n\t"
                 "@p0 st.volatile.shared.f32 [%1],%2; }"
                 :: "r"(doit), "r"(a), "f"(v));
}
__device__ __forceinline__ int isnanf_(float x) { return x != x; }

// Low-traffic wait: 32-bit probe on the slot's .x word + HW-sleep backoff.
// Spinning consumers otherwise flood the MIO/LSU queue and throttle the
// producer warp's SHFL/LDS issue on the same SM.
#define WAIT_SLOT(SLOT_) do {                                                  \
    float pr_ = lds32v((const float*)&rcons[SLOT_]);                           \
    while (isnanf_(pr_)) {                                                     \
        __nanosleep(64);                                                       \
        pr_ = lds32v((const float*)&rcons[SLOT_]);                             \
    }                                                                          \
} while (0)

// One DOUBLE timestep (states 2D -> 2D+2), LINEAR space with per-thread block
// exponent. Ghost intermediate for target u0-1: one clustered exchange per
// 2 timesteps, then pure register FMA tree. Publishes slot D_+1 (exponent
// first, data second; data .x-NaN is the readiness sentinel).
#define DSTEP(D_, Ip, I0, I1, F0, F1, CUR_, FI_) do {                          \
    float pae0 = __shfl_up_sync(0xffffffffu, ae0, 1);                          \
    float pax0 = __shfl_up_sync(0xffffffffu, ax0, 1);                          \
    float pae1 = __shfl_up_sync(0xffffffffu, ae1, 1);                          \
    float pax1 = __shfl_up_sync(0xffffffffu, ax1, 1);                          \
    if (lane == 0) { pae0 = (CUR_).x; pax0 = (CUR_).y;                         \
                     pae1 = (CUR_).z; pax1 = (CUR_).w; }                       \
    pae0 *= (FI_); pax0 *= (FI_); pae1 *= (FI_); pax1 *= (FI_);                \
    float iep = Ip.x * fmaf(pae0, teepb, pax0 * txepb);                        \
    float ixp = Ip.y * fmaf(pae1, texpb, pax1 * txxpb);                        \
    float ie0 = I0.x * fmaf(pae1, tee0b, pax1 * txe0b);                        \
    float ix0 = I0.y * fmaf(ae0, tex0, ax0 * txx0);                            \
    float ie1 = I1.x * fmaf(ae0, tee1, ax0 * txe1);                            \
    float ix1 = I1.y * fmaf(ae1, tex1, ax1 * txx1);                            \
    float nae0 = F0.x * fmaf(iep, tee0b, ixp * txe0b);                         \
    float nax0 = F0.y * fmaf(ie0, tex0, ix0 * txx0);                           \
    float nae1 = F1.x * fmaf(ie0, tee1, ix0 * txe1);                           \
    float nax1 = F1.y * fmaf(ie1, tex1, ix1 * txx1);                           \
    const float* rp_ = tab + (2 * (D_) + 5) * 8;   /* frames for double D_+2 */\
    Ip = *(const float2*)(rp_ + sop);                                          \
    I0 = *(const float2*)(rp_ + so0);                                          \
    I1 = *(const float2*)(rp_ + so1);                                          \
    F0 = *(const float2*)(rp_ + 8 + so0);                                      \
    F1 = *(const float2*)(rp_ + 8 + so1);                                      \
    ae0 = nae0; ax0 = nax0; ae1 = nae1; ax1 = nax1;                            \
    sts32v_pred(&eprod[(D_) + 1], __int_as_float(e), pubmask);                 \
    sts128v_pred(&rprod[(D_) + 1], make_float4(ae0, ax0, ae1, ax1), pubmask);  \
} while (0)

extern "C" __global__ void __launch_bounds__(256, 1)
ctccrf_fused(const float* __restrict__ em,      // (B,T,8)
             const float* __restrict__ trans,   // (8,8)
             const float* __restrict__ bos,     // (8)
             const float* __restrict__ eos,     // (8)
             const int*   __restrict__ lengths, // (B)
             const int*   __restrict__ targets, // (B,L)
             const int*   __restrict__ tlens,   // (B)
             float* __restrict__ out,
             int B, int T, int L)
{
    extern __shared__ char dsm[];
    __shared__ float s_scratch[MAXB];
    __shared__ int   s_flag;
    const int tid = threadIdx.x;
    const int RNg = (T >> 1) + 4;                          // even-state slots
    float4* dring = (float4*)dsm;                          // [3][RNg] data slots
    float*  ering = (float*)(dsm + (size_t)3 * RNg * 16);  // [3][RNg] exponents
    float*  tab   = (float*)(dsm + (size_t)3 * RNg * 20);  // [T+8][8] exp-emission

    if ((int)blockIdx.x < B) {
        const int b = blockIdx.x;
        // ---------- init: ring sentinels + exp-emission table ----------
        const float NANSENT = __int_as_float(0x7fc00000);
        for (int i = tid; i < 3 * RNg; i += 256)
            dring[i] = make_float4(NANSENT, 0.f, 0.f, 0.f);
        {
            const float* emb = em + (size_t)b * T * 8;
            for (int f = tid; f < T; f += 256) {
                float4 lo = __ldg((const float4*)(emb + f * 8));
                float4 hi = __ldg((const float4*)(emb + f * 8 + 4));
                float v0 = ex2f_(lo.x * LOG2E_F), v1 = ex2f_(lo.y * LOG2E_F);
                float v2 = ex2f_(lo.z * LOG2E_F), v3 = ex2f_(lo.w * LOG2E_F);
                float v4 = ex2f_(hi.x * LOG2E_F), v5 = ex2f_(hi.y * LOG2E_F);
                float v6 = ex2f_(hi.z * LOG2E_F), v7 = ex2f_(hi.w * LOG2E_F);
                // pair-interleaved: [s0,s4, s1,s5, s2,s6, s3,s7]
                *(float4*)(tab + f * 8)     = make_float4(v0, v4, v1, v5);
                *(float4*)(tab + f * 8 + 4) = make_float4(v2, v6, v3, v7);
            }
            if (tid < 16)     // zero the 8 pad rows
                *(float4*)(tab + (T + (tid >> 1)) * 8 + (tid & 1) * 4) =
                    make_float4(0.f, 0.f, 0.f, 0.f);
        }
        __syncthreads();

        if (tid < 128) {
            // ------- Numerator: 4 worker warps, 2 targets/thread, double-steps -------
            const int lane = tid & 31;
            const int warp = tid >> 5;
            const int u0 = warp * 64 + 2 * lane, u1 = u0 + 1;

            const int len = lengths[b];
            const int ND = (len - 1) >> 1;       // number of double-steps
            const int tg0 = __ldg(targets + b * L + u0);
            const int tg1 = __ldg(targets + b * L + u1);
            const int tgm1 = (u0 == 0) ? tg0 : __ldg(targets + b * L + u0 - 1);
            const int tgm2 = (u0 >= 2) ? __ldg(targets + b * L + u0 - 2) : tg0;
            const int so0 = 2 * tg0, so1 = 2 * tg1, sop = 2 * tgm1;
            const int pubmask = (int)(lane == 31) & (int)(warp < 3);
            const float zm = (u0 == 0) ? 0.f : 1.f;

            // transitions (linear)
            const float tee0b = zm * __expf(__ldg(trans + tgm1 * 8 + tg0));
            const float txe0b = zm * __expf(__ldg(trans + (tgm1 + 4) * 8 + tg0));
            const float teepb = zm * __expf(__ldg(trans + tgm2 * 8 + tgm1));
            const float txepb = zm * __expf(__ldg(trans + (tgm2 + 4) * 8 + tgm1));
            const float texpb = zm * __expf(__ldg(trans + tgm1 * 8 + tgm1 + 4));
            const float txxpb = zm * __expf(__ldg(trans + (tgm1 + 4) * 8 + tgm1 + 4));
            const float tex0  = __expf(__ldg(trans + tg0 * 8 + tg0 + 4));
            const float txx0  = __expf(__ldg(trans + (tg0 + 4) * 8 + tg0 + 4));
            const float tee1  = __expf(__ldg(trans + tg0 * 8 + tg1));
            const float txe1  = __expf(__ldg(trans + (tg0 + 4) * 8 + tg1));
            const float tex1  = __expf(__ldg(trans + tg1 * 8 + tg1 + 4));
            const float txx1  = __expf(__ldg(trans + (tg1 + 4) * 8 + tg1 + 4));

            float ae0 = (u0 == 0) ? __expf(__ldg(bos + tg0) + __ldg(em + (size_t)b * T * 8 + tg0)) : 0.f;
            float ax0 = 0.f, ae1 = 0.f, ax1 = 0.f;
            int e = 0;
            int zf = (u0 != 0);

            float4*       rprod = dring + (size_t)((warp < 3) ? warp : 0) * RNg;
            const float4* rcons = dring + (size_t)((warp > 0) ? (warp - 1) : 0) * RNg;
            float*        eprod = ering + (size_t)((warp < 3) ? warp : 0) * RNg;
            const float*  econs = ering + (size_t)((warp > 0) ? (warp - 1) : 0) * RNg;

            // publish initial slot 0 (state t=0): exponent first, data second
            if (lane == 31 && warp < 3) {
                sts32v(&eprod[0], __int_as_float(0));
                sts128v(&rprod[0], make_float4(ae0, ax0, ae1, ax1));
            }

            // prime emission buffers: bufA = double 0 (frames 1,2), bufB = double 1 (3,4)
            float2 Ipa = *(const float2*)(tab + 8 + sop);
            float2 I0a = *(const float2*)(tab + 8 + so0);
            float2 I1a = *(const float2*)(tab + 8 + so1);
            float2 F0a = *(const float2*)(tab + 16 + so0);
            float2 F1a = *(const float2*)(tab + 16 + so1);
            float2 Ipb = *(const float2*)(tab + 24 + sop);
            float2 I0b = *(const float2*)(tab + 24 + so0);
            float2 I1b = *(const float2*)(tab + 24 + so1);
            float2 F0b = *(const float2*)(tab + 32 + so0);
            float2 F1b = *(const float2*)(tab + 32 + so1);

            float4 cur0 = make_float4(0.f,0.f,0.f,0.f), cur1 = cur0;

            int d = 0;
            for (; d + 1 < ND; d += 2) {
                int e0i = e, e1i = e;
                if (warp > 0) {
                    // probe ONLY the last slot; producer publishes in order,
                    // so slot d is ready once slot d+1 is.
                    WAIT_SLOT(d + 1);
                    cur0 = lds128v(&rcons[d]);
                    cur1 = lds128v(&rcons[d + 1]);
                    e0i = __float_as_int(lds32v(&econs[d]));
                    e1i = __float_as_int(lds32v(&econs[d + 1]));
                }
                int eprev = __shfl_up_sync(0xffffffffu, e, 1);
                int eup = (lane == 0) ? e0i : eprev;
                e = zf ? eup : e;
                int s0 = ((lane == 0) ? e0i : eprev) - e;
                int s1 = ((lane == 0) ? e1i : eprev) - e;
                float fi0 = __int_as_float((min(max(s0, -126), 90) + 127) << 23);
                float fi1 = __int_as_float((min(max(s1, -126), 90) + 127) << 23);

                DSTEP(d,     Ipa, I0a, I1a, F0a, F1a, cur0, fi0);
                DSTEP(d + 1, Ipb, I0b, I1b, F0b, F1b, cur1, fi1);

                // group rescale
                float m_ = fmaxf(fmaxf(ae0, ax0), fmaxf(ae1, ax1));
                int mb_ = __float_as_int(m_);
                zf = (mb_ == 0);
                int ei_ = zf ? 0 : ((mb_ >> 23) - 127);
                float fr_ = __int_as_float((127 - ei_) << 23);
                ae0 *= fr_; ax0 *= fr_; ae1 *= fr_; ax1 *= fr_;
                e += ei_;
            }
            // remainder double (ND odd)
            if (d < ND) {
                int e0i = e;
                if (warp > 0) {
                    WAIT_SLOT(d);
                    cur0 = lds128v(&rcons[d]);
                    e0i = __float_as_int(lds32v(&econs[d]));
                }
                int eprev = __shfl_up_sync(0xffffffffu, e, 1);
                int eup = (lane == 0) ? e0i : eprev;
                e = zf ? eup : e;
                int s0 = ((lane == 0) ? e0i : eprev) - e;
                float fi0 = __int_as_float((min(max(s0, -126), 90) + 127) << 23);
                DSTEP(d, Ipa, I0a, I1a, F0a, F1a, cur0, fi0);
                d++;
            }
            // tail single step (len-1 odd): state 2*ND -> len-1, frame len-1
            if ((len - 1) & 1) {
                float4 bb = make_float4(0.f,0.f,0.f,0.f);
                int ebi = e;
                if (warp > 0) {
                    WAIT_SLOT(ND);
                    bb = lds128v(&rcons[ND]);
                    ebi = __float_as_int(lds32v(&econs[ND]));
                }
                int eprev = __shfl_up_sync(0xffffffffu, e, 1);
                int ss = ((lane == 0) ? ebi : eprev) - e;
                float fib = __int_as_float((min(max(ss, -126), 90) + 127) << 23);
                float pe = __shfl_up_sync(0xffffffffu, ae1, 1);
                float px = __shfl_up_sync(0xffffffffu, ax1, 1);
                if (lane == 0) { pe = bb.z; px = bb.w; }
                pe *= fib; px *= fib;
                const float* tpf = tab + (len - 1) * 8;
                float2 Ef0 = *(const float2*)(tpf + so0);
                float2 Ef1 = *(const float2*)(tpf + so1);
                float nae0 = Ef0.x * fmaf(pe, tee0b, px * txe0b);
                float nax0 = Ef0.y * fmaf(ae0, tex0, ax0 * txx0);
                float nae1 = Ef1.x * fmaf(ae0, tee1, ax0 * txe1);
                float nax1 = Ef1.y * fmaf(ae1, tex1, ax1 * txx1);
                ae0 = nae0; ax0 = nax0; ae1 = nae1; ax1 = nax1;
            }

            // ---- final logsumexp for the terminal target ----
            const int tl = __ldg(tlens + b);
            const int uf = tl - 1;
            if (u0 == uf) {
                float fe2 = (ae0 > 0.f ? lg2f_(ae0) : NEGF) + (float)e + __ldg(eos + tg0) * LOG2E_F;
                float fx2 = (ax0 > 0.f ? lg2f_(ax0) : NEGF) + (float)e + __ldg(eos + tg0 + 4) * LOG2E_F;
                g_num[b] = lae2(fe2, fx2) * LN2_F;
            }
            if (u1 == uf) {
                float fe2 = (ae1 > 0.f ? lg2f_(ae1) : NEGF) + (float)e + __ldg(eos + tg1) * LOG2E_F;
                float fx2 = (ax1 > 0.f ? lg2f_(ax1) : NEGF) + (float)e + __ldg(eos + tg1 + 4) * LOG2E_F;
                g_num[b] = lae2(fe2, fx2) * LN2_F;
            }
        }
    } else {
        // ------------- Denominator Phase A: chunked 8x8 linear-space scan -------------
        const int db = blockIdx.x - B;
        const int c = tid >> 3;
        const int i = tid & 7;
        const int len = lengths[db];
        const int C = (T - 1 + NCH - 1) / NCH;

        float E[64];
        #pragma unroll
        for (int k = 0; k < 64; ++k) E[k] = __expf(__ldg(trans + k));

        float r[8];
        #pragma unroll
        for (int j = 0; j < 8; ++j) r[j] = (j == i) ? 1.0f : 0.0f;
        float off = 0.0f;

        const int t0 = 1 + c * C;
        const int t1 = min(t0 + C, len);
        const float* emb = em + (size_t)db * T * 8;

        for (int t = t0; t < t1; ++t) {
            float4 lo = __ldg((const float4*)(emb + t * 8));
            float4 hi = __ldg((const float4*)(emb + t * 8 + 4));
            float Em[8];
            Em[0] = __expf(lo.x); Em[1] = __expf(lo.y);
            Em[2] = __expf(lo.z); Em[3] = __expf(lo.w);
            Em[4] = __expf(hi.x); Em[5] = __expf(hi.y);
            Em[6] = __expf(hi.z); Em[7] = __expf(hi.w);

            float s[8];
            #pragma unroll
            for (int j = 0; j < 8; ++j) {
                float acc = r[0] * E[0 * 8 + j];
                #pragma unroll
                for (int kk = 1; kk < 8; ++kk) acc = fmaf(r[kk], E[kk * 8 + j], acc);
                s[j] = acc * Em[j];
            }
            #pragma unroll
            for (int j = 0; j < 8; ++j) r[j] = s[j];

            if (((t - t0) & 3) == 3) {
                float m = r[0];
                #pragma unroll
                for (int j = 1; j < 8; ++j) m = fmaxf(m, r[j]);
                float inv = __fdividef(1.0f, m);
                off += __logf(m);
                #pragma unroll
                for (int j = 0; j < 8; ++j) r[j] *= inv;
            }
        }

        #pragma unroll
        for (int j = 0; j < 8; ++j) {
            float lv = (r[j] > 0.0f) ? (__logf(r[j]) + off) : NEGF;
            g_LP[(((db * NCH) + c) * 8 + j) * 8 + i] = lv;
        }
    }

    // ---------------- Fused finish: last block folds chunks + reduces ----------------
    __threadfence();
    __syncthreads();
    if (tid == 0) {
        unsigned old = atomicAdd(&g_done, 1u);
        s_flag = (old == (unsigned)(2 * B - 1));
    }
    __syncthreads();
    if (s_flag) {
        __threadfence();
        const int  bq = min(tid >> 3, B - 1);
        const int  j  = tid & 7;
        const bool active = (tid >> 3) < B;

        float alpha = __ldg(bos + j) + __ldg(em + (size_t)bq * T * 8 + j);
        const float* base = g_LP + (size_t)bq * NCH * 64 + j * 8;
        float4 plo[4], phi[4];
        #pragma unroll
        for (int kk = 0; kk < 4; ++kk) {
            plo[kk] = __ldg((const float4*)(base + kk * 64));
            phi[kk] = __ldg((const float4*)(base + kk * 64 + 4));
        }
        #pragma unroll 4
        for (int c = 0; c < NCH; ++c) {
            float4 lo = plo[c & 3], hi = phi[c & 3];
            int cn = c + 4;
            if (cn < NCH) {
                plo[c & 3] = __ldg((const float4*)(base + cn * 64));
                phi[c & 3] = __ldg((const float4*)(base + cn * 64 + 4));
            }
            float M[8] = {lo.x, lo.y, lo.z, lo.w, hi.x, hi.y, hi.z, hi.w};
            float v[8], m = -3.0e38f;
            #pragma unroll
            for (int i2 = 0; i2 < 8; ++i2) {
                float ai = __shfl_sync(0xffffffffu, alpha, i2, 8);
                v[i2] = ai + M[i2];
                m = fmaxf(m, v[i2]);
            }
            float s = 0.0f;
            #pragma unroll
            for (int i2 = 0; i2 < 8; ++i2) s += ex2f_((v[i2] - m) * LOG2E_F);
            alpha = m + lg2f_(s) * LN2_F;
        }
        float f = alpha + __ldg(eos + j);
        float m = f;
        #pragma unroll
        for (int d2 = 4; d2 >= 1; d2 >>= 1) m = fmaxf(m, __shfl_xor_sync(0xffffffffu, m, d2, 8));
        float s = ex2f_((f - m) * LOG2E_F);
        #pragma unroll
        for (int d2 = 4; d2 >= 1; d2 >>= 1) s += __shfl_xor_sync(0xffffffffu, s, d2, 8);
        float den = m + lg2f_(s) * LN2_F;

        if (active && j == 0) s_scratch[tid >> 3] = den - g_num[bq];
        __syncthreads();
        if (tid == 0) {
            float acc = 0.0f;
            for (int bb = 0; bb < B; ++bb) acc += s_scratch[bb];
            out[0] = acc / (float)B;
            g_done = 0;
        }
    }
}

extern "C" void kernel_launch(void* const* d_in, const int* in_sizes, int n_in,
                              void* d_out, int out_size)
{
    const float* em     = (const float*)d_in[0];  // (B,T,8)
    const float* trans  = (const float*)d_in[1];  // (8,8)
    const float* bos    = (const float*)d_in[2];  // (8)
    const float* eos    = (const float*)d_in[3];  // (8)
    const int*   lens   = (const int*)  d_in[4];  // (B)
    const int*   tgts   = (const int*)  d_in[5];  // (B,L)
    const int*   tlens  = (const int*)  d_in[6];  // (B)
    float* out = (float*)d_out;

    const int B = in_sizes[4];                 // 16
    const int T = in_sizes[0] / (B * 8);       // 2048
    const int L = in_sizes[5] / B;             // 256

    const int RNg = (T >> 1) + 4;
    const size_t smem = (size_t)3 * RNg * 20 + (size_t)(T + 8) * 8 * sizeof(float);
    cudaFuncSetAttribute(ctccrf_fused, cudaFuncAttributeMaxDynamicSharedMemorySize, (int)smem);

    // Blocks [0,B): numerator (4 worker warps, double-steps, low-traffic polls).
    // Blocks [B,2B): denominator phase A. Last-done block runs the finish fold.
    ctccrf_fused<<<2 * B, 256, smem>>>(em, trans, bos, eos, lens, tgts, tlens, out, B, T, L);
}

// round 14
// speedup vs baseline: 1.1224x; 1.1224x over previous
#include <cuda_runtime.h>
#include <math.h>

#define NEGF    (-1e30f)
#define MAXB    16
#define NCH     32
#define LOG2E_F 1.4426950408889634f
#define LN2_F   0.6931471805599453f

// Scratch (static device arrays; no allocations allowed)
__device__ float    g_num[MAXB];                 // numerator logZ per batch (natural log)
__device__ float    g_LP[MAXB * NCH * 8 * 8];    // [b][c][j][i] log chunk matrices
__device__ unsigned g_done = 0;

// ---------------- helpers ----------------
__device__ __forceinline__ float ex2f_(float x) {
    float r; asm("ex2.approx.ftz.f32 %0, %1;" : "=f"(r) : "f"(x)); return r;
}
__device__ __forceinline__ float lg2f_(float x) {
    float r; asm("lg2.approx.ftz.f32 %0, %1;" : "=f"(r) : "f"(x)); return r;
}
__device__ __forceinline__ float lae2(float a, float b) {
    float m = fmaxf(a, b);
    float d = fminf(a, b) - m;
    return m + lg2f_(1.0f + ex2f_(d));
}
// Volatile ring ops WITHOUT "memory" clobbers: asm volatile + PTX .volatile
// keep these ops ordered among themselves and never elided, but let ptxas
// software-pipeline the surrounding non-volatile work (emission LDS, FMA
// trees, shfls) ACROSS step boundaries. The "memory" clobber was acting as a
// full compiler barrier every step -- the hidden serializer since R8.
__device__ __forceinline__ float4 lds128v(const float4* p) {
    float4 v; unsigned a = (unsigned)__cvta_generic_to_shared(p);
    asm volatile("ld.volatile.shared.v4.f32 {%0,%1,%2,%3},[%4];"
                 : "=f"(v.x), "=f"(v.y), "=f"(v.z), "=f"(v.w) : "r"(a));
    return v;
}
__device__ __forceinline__ float lds32v(const float* p) {
    float v; unsigned a = (unsigned)__cvta_generic_to_shared(p);
    asm volatile("ld.volatile.shared.f32 %0,[%1];" : "=f"(v) : "r"(a));
    return v;
}
__device__ __forceinline__ void sts128v(float4* p, float4 v) {
    unsigned a = (unsigned)__cvta_generic_to_shared(p);
    asm volatile("st.volatile.shared.v4.f32 [%0],{%1,%2,%3,%4};"
                 :: "r"(a), "f"(v.x), "f"(v.y), "f"(v.z), "f"(v.w));
}
__device__ __forceinline__ void sts32v(float* p, float v) {
    unsigned a = (unsigned)__cvta_generic_to_shared(p);
    asm volatile("st.volatile.shared.f32 [%0],%1;" :: "r"(a), "f"(v));
}
__device__ __forceinline__ void sts128v_pred(float4* p, float4 v, int doit) {
    unsigned a = (unsigned)__cvta_generic_to_shared(p);
    asm volatile("{ .reg .pred p0;\n\t"
                 "setp.ne.u32 p0, %0, 0;\n\t"
                 "@p0 st.volatile.shared.v4.f32 [%1],{%2,%3,%4,%5}; }"
                 :: "r"(doit), "r"(a), "f"(v.x), "f"(v.y), "f"(v.z), "f"(v.w));
}
__device__ __forceinline__ void sts32v_pred(float* p, float v, int doit) {
    unsigned a = (unsigned)__cvta_generic_to_shared(p);
    asm volatile("{ .reg .pred p0;\n\t"
                 "setp.ne.u32 p0, %0, 0;\n\t"
                 "@p0 st.volatile.shared.f32 [%1],%2; }"
                 :: "r"(doit), "r"(a), "f"(v));
}
__device__ __forceinline__ int isnanf_(float x) { return x != x; }

// Low-traffic wait: 32-bit probe on the slot's .x word; HW-sleep on miss
// (cold path -- steady-state consumers lag the producer and hit first try).
#define WAIT_SLOT(SLOT_) do {                                                  \
    float pr_ = lds32v((const float*)&rcons[SLOT_]);                           \
    while (isnanf_(pr_)) {                                                     \
        __nanosleep(64);                                                       \
        pr_ = lds32v((const float*)&rcons[SLOT_]);                             \
    }                                                                          \
} while (0)

// One DOUBLE timestep (states 2D -> 2D+2), LINEAR space with per-thread block
// exponent. Ghost intermediate for target u0-1: one clustered exchange per
// 2 timesteps, then pure register FMA tree. Publishes slot D_+1 (exponent
// first, data second; data .x-NaN is the readiness sentinel).
#define DSTEP(D_, Ip, I0, I1, F0, F1, CUR_, FI_) do {                          \
    float pae0 = __shfl_up_sync(0xffffffffu, ae0, 1);                          \
    float pax0 = __shfl_up_sync(0xffffffffu, ax0, 1);                          \
    float pae1 = __shfl_up_sync(0xffffffffu, ae1, 1);                          \
    float pax1 = __shfl_up_sync(0xffffffffu, ax1, 1);                          \
    if (lane == 0) { pae0 = (CUR_).x; pax0 = (CUR_).y;                         \
                     pae1 = (CUR_).z; pax1 = (CUR_).w; }                       \
    pae0 *= (FI_); pax0 *= (FI_); pae1 *= (FI_); pax1 *= (FI_);                \
    float iep = Ip.x * fmaf(pae0, teepb, pax0 * txepb);                        \
    float ixp = Ip.y * fmaf(pae1, texpb, pax1 * txxpb);                        \
    float ie0 = I0.x * fmaf(pae1, tee0b, pax1 * txe0b);                        \
    float ix0 = I0.y * fmaf(ae0, tex0, ax0 * txx0);                            \
    float ie1 = I1.x * fmaf(ae0, tee1, ax0 * txe1);                            \
    float ix1 = I1.y * fmaf(ae1, tex1, ax1 * txx1);                            \
    float nae0 = F0.x * fmaf(iep, tee0b, ixp * txe0b);                         \
    float nax0 = F0.y * fmaf(ie0, tex0, ix0 * txx0);                           \
    float nae1 = F1.x * fmaf(ie0, tee1, ix0 * txe1);                           \
    float nax1 = F1.y * fmaf(ie1, tex1, ix1 * txx1);                           \
    const float* rp_ = tab + (2 * (D_) + 5) * 8;   /* frames for double D_+2 */\
    Ip = *(const float2*)(rp_ + sop);                                          \
    I0 = *(const float2*)(rp_ + so0);                                          \
    I1 = *(const float2*)(rp_ + so1);                                          \
    F0 = *(const float2*)(rp_ + 8 + so0);                                      \
    F1 = *(const float2*)(rp_ + 8 + so1);                                      \
    ae0 = nae0; ax0 = nax0; ae1 = nae1; ax1 = nax1;                            \
    sts32v_pred(&eprod[(D_) + 1], __int_as_float(e), pubmask);                 \
    sts128v_pred(&rprod[(D_) + 1], make_float4(ae0, ax0, ae1, ax1), pubmask);  \
} while (0)

extern "C" __global__ void __launch_bounds__(256, 1)
ctccrf_fused(const float* __restrict__ em,      // (B,T,8)
             const float* __restrict__ trans,   // (8,8)
             const float* __restrict__ bos,     // (8)
             const float* __restrict__ eos,     // (8)
             const int*   __restrict__ lengths, // (B)
             const int*   __restrict__ targets, // (B,L)
             const int*   __restrict__ tlens,   // (B)
             float* __restrict__ out,
             int B, int T, int L)
{
    extern __shared__ char dsm[];
    __shared__ float s_scratch[MAXB];
    __shared__ int   s_flag;
    const int tid = threadIdx.x;
    const int RNg = (T >> 1) + 4;                          // even-state slots
    float4* dring = (float4*)dsm;                          // [4][RNg] data slots (row 0 = dummy)
    float*  ering = (float*)(dsm + (size_t)4 * RNg * 16);  // [4][RNg] exponents
    float*  tab   = (float*)(dsm + (size_t)4 * RNg * 20);  // [T+8][8] exp-emission

    if ((int)blockIdx.x < B) {
        const int b = blockIdx.x;
        // ---------- init: dummy row 0 (always ready, zeros) + NaN rows 1-3 + table ----------
        const float NANSENT = __int_as_float(0x7fc00000);
        for (int i = tid; i < 4 * RNg; i += 256) {
            dring[i] = (i < RNg) ? make_float4(0.f, 0.f, 0.f, 0.f)
                                 : make_float4(NANSENT, 0.f, 0.f, 0.f);
            ering[i] = 0.f;
        }
        {
            const float* emb = em + (size_t)b * T * 8;
            for (int f = tid; f < T; f += 256) {
                float4 lo = __ldg((const float4*)(emb + f * 8));
                float4 hi = __ldg((const float4*)(emb + f * 8 + 4));
                float v0 = ex2f_(lo.x * LOG2E_F), v1 = ex2f_(lo.y * LOG2E_F);
                float v2 = ex2f_(lo.z * LOG2E_F), v3 = ex2f_(lo.w * LOG2E_F);
                float v4 = ex2f_(hi.x * LOG2E_F), v5 = ex2f_(hi.y * LOG2E_F);
                float v6 = ex2f_(hi.z * LOG2E_F), v7 = ex2f_(hi.w * LOG2E_F);
                // pair-interleaved: [s0,s4, s1,s5, s2,s6, s3,s7]
                *(float4*)(tab + f * 8)     = make_float4(v0, v4, v1, v5);
                *(float4*)(tab + f * 8 + 4) = make_float4(v2, v6, v3, v7);
            }
            if (tid < 16)     // zero the 8 pad rows
                *(float4*)(tab + (T + (tid >> 1)) * 8 + (tid & 1) * 4) =
                    make_float4(0.f, 0.f, 0.f, 0.f);
        }
        __syncthreads();

        if (tid < 128) {
            // ------- Numerator: 4 worker warps, 2 targets/thread, double-steps -------
            const int lane = tid & 31;
            const int warp = tid >> 5;
            const int u0 = warp * 64 + 2 * lane, u1 = u0 + 1;

            const int len = lengths[b];
            const int ND = (len - 1) >> 1;       // number of double-steps
            const int tg0 = __ldg(targets + b * L + u0);
            const int tg1 = __ldg(targets + b * L + u1);
            const int tgm1 = (u0 == 0) ? tg0 : __ldg(targets + b * L + u0 - 1);
            const int tgm2 = (u0 >= 2) ? __ldg(targets + b * L + u0 - 2) : tg0;
            const int so0 = 2 * tg0, so1 = 2 * tg1, sop = 2 * tgm1;
            const int pubmask = (int)(lane == 31) & (int)(warp < 3);
            const float zm = (u0 == 0) ? 0.f : 1.f;

            // transitions (linear)
            const float tee0b = zm * __expf(__ldg(trans + tgm1 * 8 + tg0));
            const float txe0b = zm * __expf(__ldg(trans + (tgm1 + 4) * 8 + tg0));
            const float teepb = zm * __expf(__ldg(trans + tgm2 * 8 + tgm1));
            const float txepb = zm * __expf(__ldg(trans + (tgm2 + 4) * 8 + tgm1));
            const float texpb = zm * __expf(__ldg(trans + tgm1 * 8 + tgm1 + 4));
            const float txxpb = zm * __expf(__ldg(trans + (tgm1 + 4) * 8 + tgm1 + 4));
            const float tex0  = __expf(__ldg(trans + tg0 * 8 + tg0 + 4));
            const float txx0  = __expf(__ldg(trans + (tg0 + 4) * 8 + tg0 + 4));
            const float tee1  = __expf(__ldg(trans + tg0 * 8 + tg1));
            const float txe1  = __expf(__ldg(trans + (tg0 + 4) * 8 + tg1));
            const float tex1  = __expf(__ldg(trans + tg1 * 8 + tg1 + 4));
            const float txx1  = __expf(__ldg(trans + (tg1 + 4) * 8 + tg1 + 4));

            float ae0 = (u0 == 0) ? __expf(__ldg(bos + tg0) + __ldg(em + (size_t)b * T * 8 + tg0)) : 0.f;
            float ax0 = 0.f, ae1 = 0.f, ax1 = 0.f;
            int e = 0;
            int zf = (u0 != 0);

            // ring rows: warp w consumes row w (row 0 = always-ready dummy),
            // produces row w+1 (clamped; warp 3 never stores, pubmask = 0).
            const int prow = min(warp + 1, 3);
            float4*       rprod = dring + (size_t)prow * RNg;
            const float4* rcons = dring + (size_t)warp * RNg;
            float*        eprod = ering + (size_t)prow * RNg;
            const float*  econs = ering + (size_t)warp * RNg;

            // publish initial slot 0 (state t=0): exponent first, data second
            if (lane == 31 && warp < 3) {
                sts32v(&eprod[0], __int_as_float(0));
                sts128v(&rprod[0], make_float4(ae0, ax0, ae1, ax1));
            }

            // prime emission buffers: bufA = double 0 (frames 1,2), bufB = double 1 (3,4)
            float2 Ipa = *(const float2*)(tab + 8 + sop);
            float2 I0a = *(const float2*)(tab + 8 + so0);
            float2 I1a = *(const float2*)(tab + 8 + so1);
            float2 F0a = *(const float2*)(tab + 16 + so0);
            float2 F1a = *(const float2*)(tab + 16 + so1);
            float2 Ipb = *(const float2*)(tab + 24 + sop);
            float2 I0b = *(const float2*)(tab + 24 + so0);
            float2 I1b = *(const float2*)(tab + 24 + so1);
            float2 F0b = *(const float2*)(tab + 32 + so0);
            float2 F1b = *(const float2*)(tab + 32 + so1);

            float4 cur0, cur1;

            int d = 0;
            for (; d + 1 < ND; d += 2) {
                // branch-free handoff: every warp polls; warp 0 hits the
                // always-ready dummy row. Producer publishes in order, so
                // probing the LAST slot covers both.
                WAIT_SLOT(d + 1);
                cur0 = lds128v(&rcons[d]);
                cur1 = lds128v(&rcons[d + 1]);
                int e0i = __float_as_int(lds32v(&econs[d]));
                int e1i = __float_as_int(lds32v(&econs[d + 1]));

                int eprev = __shfl_up_sync(0xffffffffu, e, 1);
                int eup = (lane == 0) ? e0i : eprev;
                e = zf ? eup : e;
                int s0 = ((lane == 0) ? e0i : eprev) - e;
                int s1 = ((lane == 0) ? e1i : eprev) - e;
                float fi0 = __int_as_float((min(max(s0, -126), 90) + 127) << 23);
                float fi1 = __int_as_float((min(max(s1, -126), 90) + 127) << 23);

                DSTEP(d,     Ipa, I0a, I1a, F0a, F1a, cur0, fi0);
                DSTEP(d + 1, Ipb, I0b, I1b, F0b, F1b, cur1, fi1);

                // group rescale
                float m_ = fmaxf(fmaxf(ae0, ax0), fmaxf(ae1, ax1));
                int mb_ = __float_as_int(m_);
                zf = (mb_ == 0);
                int ei_ = zf ? 0 : ((mb_ >> 23) - 127);
                float fr_ = __int_as_float((127 - ei_) << 23);
                ae0 *= fr_; ax0 *= fr_; ae1 *= fr_; ax1 *= fr_;
                e += ei_;
            }
            // remainder double (ND odd)
            if (d < ND) {
                WAIT_SLOT(d);
                cur0 = lds128v(&rcons[d]);
                int e0i = __float_as_int(lds32v(&econs[d]));
                int eprev = __shfl_up_sync(0xffffffffu, e, 1);
                int eup = (lane == 0) ? e0i : eprev;
                e = zf ? eup : e;
                int s0 = ((lane == 0) ? e0i : eprev) - e;
                float fi0 = __int_as_float((min(max(s0, -126), 90) + 127) << 23);
                DSTEP(d, Ipa, I0a, I1a, F0a, F1a, cur0, fi0);
                d++;
            }
            // tail single step (len-1 odd): state 2*ND -> len-1, frame len-1
            if ((len - 1) & 1) {
                WAIT_SLOT(ND);
                float4 bb = lds128v(&rcons[ND]);
                int ebi = __float_as_int(lds32v(&econs[ND]));
                int eprev = __shfl_up_sync(0xffffffffu, e, 1);
                int ss = ((lane == 0) ? ebi : eprev) - e;
                float fib = __int_as_float((min(max(ss, -126), 90) + 127) << 23);
                float pe = __shfl_up_sync(0xffffffffu, ae1, 1);
                float px = __shfl_up_sync(0xffffffffu, ax1, 1);
                if (lane == 0) { pe = bb.z; px = bb.w; }
                pe *= fib; px *= fib;
                const float* tpf = tab + (len - 1) * 8;
                float2 Ef0 = *(const float2*)(tpf + so0);
                float2 Ef1 = *(const float2*)(tpf + so1);
                float nae0 = Ef0.x * fmaf(pe, tee0b, px * txe0b);
                float nax0 = Ef0.y * fmaf(ae0, tex0, ax0 * txx0);
                float nae1 = Ef1.x * fmaf(ae0, tee1, ax0 * txe1);
                float nax1 = Ef1.y * fmaf(ae1, tex1, ax1 * txx1);
                ae0 = nae0; ax0 = nax0; ae1 = nae1; ax1 = nax1;
            }

            // ---- final logsumexp for the terminal target ----
            const int tl = __ldg(tlens + b);
            const int uf = tl - 1;
            if (u0 == uf) {
                float fe2 = (ae0 > 0.f ? lg2f_(ae0) : NEGF) + (float)e + __ldg(eos + tg0) * LOG2E_F;
                float fx2 = (ax0 > 0.f ? lg2f_(ax0) : NEGF) + (float)e + __ldg(eos + tg0 + 4) * LOG2E_F;
                g_num[b] = lae2(fe2, fx2) * LN2_F;
            }
            if (u1 == uf) {
                float fe2 = (ae1 > 0.f ? lg2f_(ae1) : NEGF) + (float)e + __ldg(eos + tg1) * LOG2E_F;
                float fx2 = (ax1 > 0.f ? lg2f_(ax1) : NEGF) + (float)e + __ldg(eos + tg1 + 4) * LOG2E_F;
                g_num[b] = lae2(fe2, fx2) * LN2_F;
            }
        }
    } else {
        // ------------- Denominator Phase A: chunked 8x8 linear-space scan -------------
        const int db = blockIdx.x - B;
        const int c = tid >> 3;
        const int i = tid & 7;
        const int len = lengths[db];
        const int C = (T - 1 + NCH - 1) / NCH;

        float E[64];
        #pragma unroll
        for (int k = 0; k < 64; ++k) E[k] = __expf(__ldg(trans + k));

        float r[8];
        #pragma unroll
        for (int j = 0; j < 8; ++j) r[j] = (j == i) ? 1.0f : 0.0f;
        float off = 0.0f;

        const int t0 = 1 + c * C;
        const int t1 = min(t0 + C, len);
        const float* emb = em + (size_t)db * T * 8;

        for (int t = t0; t < t1; ++t) {
            float4 lo = __ldg((const float4*)(emb + t * 8));
            float4 hi = __ldg((const float4*)(emb + t * 8 + 4));
            float Em[8];
            Em[0] = __expf(lo.x); Em[1] = __expf(lo.y);
            Em[2] = __expf(lo.z); Em[3] = __expf(lo.w);
            Em[4] = __expf(hi.x); Em[5] = __expf(hi.y);
            Em[6] = __expf(hi.z); Em[7] = __expf(hi.w);

            float s[8];
            #pragma unroll
            for (int j = 0; j < 8; ++j) {
                float acc = r[0] * E[0 * 8 + j];
                #pragma unroll
                for (int kk = 1; kk < 8; ++kk) acc = fmaf(r[kk], E[kk * 8 + j], acc);
                s[j] = acc * Em[j];
            }
            #pragma unroll
            for (int j = 0; j < 8; ++j) r[j] = s[j];

            if (((t - t0) & 3) == 3) {
                float m = r[0];
                #pragma unroll
                for (int j = 1; j < 8; ++j) m = fmaxf(m, r[j]);
                float inv = __fdividef(1.0f, m);
                off += __logf(m);
                #pragma unroll
                for (int j = 0; j < 8; ++j) r[j] *= inv;
            }
        }

        #pragma unroll
        for (int j = 0; j < 8; ++j) {
            float lv = (r[j] > 0.0f) ? (__logf(r[j]) + off) : NEGF;
            g_LP[(((db * NCH) + c) * 8 + j) * 8 + i] = lv;
        }
    }

    // ---------------- Fused finish: last block folds chunks + reduces ----------------
    __threadfence();
    __syncthreads();
    if (tid == 0) {
        unsigned old = atomicAdd(&g_done, 1u);
        s_flag = (old == (unsigned)(2 * B - 1));
    }
    __syncthreads();
    if (s_flag) {
        __threadfence();
        const int  bq = min(tid >> 3, B - 1);
        const int  j  = tid & 7;
        const bool active = (tid >> 3) < B;

        float alpha = __ldg(bos + j) + __ldg(em + (size_t)bq * T * 8 + j);
        const float* base = g_LP + (size_t)bq * NCH * 64 + j * 8;
        float4 plo[4], phi[4];
        #pragma unroll
        for (int kk = 0; kk < 4; ++kk) {
            plo[kk] = __ldg((const float4*)(base + kk * 64));
            phi[kk] = __ldg((const float4*)(base + kk * 64 + 4));
        }
        #pragma unroll 4
        for (int c = 0; c < NCH; ++c) {
            float4 lo = plo[c & 3], hi = phi[c & 3];
            int cn = c + 4;
            if (cn < NCH) {
                plo[c & 3] = __ldg((const float4*)(base + cn * 64));
                phi[c & 3] = __ldg((const float4*)(base + cn * 64 + 4));
            }
            float M[8] = {lo.x, lo.y, lo.z, lo.w, hi.x, hi.y, hi.z, hi.w};
            float v[8], m = -3.0e38f;
            #pragma unroll
            for (int i2 = 0; i2 < 8; ++i2) {
                float ai = __shfl_sync(0xffffffffu, alpha, i2, 8);
                v[i2] = ai + M[i2];
                m = fmaxf(m, v[i2]);
            }
            float s = 0.0f;
            #pragma unroll
            for (int i2 = 0; i2 < 8; ++i2) s += ex2f_((v[i2] - m) * LOG2E_F);
            alpha = m + lg2f_(s) * LN2_F;
        }
        float f = alpha + __ldg(eos + j);
        float m = f;
        #pragma unroll
        for (int d2 = 4; d2 >= 1; d2 >>= 1) m = fmaxf(m, __shfl_xor_sync(0xffffffffu, m, d2, 8));
        float s = ex2f_((f - m) * LOG2E_F);
        #pragma unroll
        for (int d2 = 4; d2 >= 1; d2 >>= 1) s += __shfl_xor_sync(0xffffffffu, s, d2, 8);
        float den = m + lg2f_(s) * LN2_F;

        if (active && j == 0) s_scratch[tid >> 3] = den - g_num[bq];
        __syncthreads();
        if (tid == 0) {
            float acc = 0.0f;
            for (int bb = 0; bb < B; ++bb) acc += s_scratch[bb];
            out[0] = acc / (float)B;
            g_done = 0;
        }
    }
}

extern "C" void kernel_launch(void* const* d_in, const int* in_sizes, int n_in,
                              void* d_out, int out_size)
{
    const float* em     = (const float*)d_in[0];  // (B,T,8)
    const float* trans  = (const float*)d_in[1];  // (8,8)
    const float* bos    = (const float*)d_in[2];  // (8)
    const float* eos    = (const float*)d_in[3];  // (8)
    const int*   lens   = (const int*)  d_in[4];  // (B)
    const int*   tgts   = (const int*)  d_in[5];  // (B,L)
    const int*   tlens  = (const int*)  d_in[6];  // (B)
    float* out = (float*)d_out;

    const int B = in_sizes[4];                 // 16
    const int T = in_sizes[0] / (B * 8);       // 2048
    const int L = in_sizes[5] / B;             // 256

    const int RNg = (T >> 1) + 4;
    // dynamic smem: data ring [4][RNg] float4 + exp ring [4][RNg] float
    //               + padded exp-emission table [T+8][8] float
    const size_t smem = (size_t)4 * RNg * 20 + (size_t)(T + 8) * 8 * sizeof(float);
    cudaFuncSetAttribute(ctccrf_fused, cudaFuncAttributeMaxDynamicSharedMemorySize, (int)smem);

    // Blocks [0,B): numerator (4 worker warps, clobber-free ring, branch-free loop).
    // Blocks [B,2B): denominator phase A. Last-done block runs the finish fold.
    ctccrf_fused<<<2 * B, 256, smem>>>(em, trans, bos, eos, lens, tgts, tlens, out, B, T, L);
}